// round 16
// baseline (speedup 1.0000x reference)
#include <cuda_runtime.h>
#include <math.h>

#define BATCH 8192
#define NSTEP 256

#define K_DT      0.01f
#define K_HDT     0.005f
#define K_A2      0.0025f
#define K_DT6     ((float)(0.01/6.0))
#define K_DT12    (K_DT6 * 0.5f)
#define K_DT22    (0.5f * K_DT * K_DT)
#define K_INV_M   (1.0f/0.033f)
#define K_MG      (0.033f*9.81f)
#define K_KT      3.8e-8f
#define K_KTARM   ((float)(3.8e-8*0.04))
#define K_KC      3.8e-11f
#define K_JX      1.4e-5f
#define K_JZ      2.17e-5f
#define K_INV_JX  (1.0f/1.4e-5f)
#define K_INV_JZ  (1.0f/2.17e-5f)
#define K_C1      ((K_JX - K_JZ) * K_INV_JX)
#define K_C2      ((K_JZ - K_JX) * K_INV_JX)

#define F_PI      3.14159265358979f
#define F_PIO2    1.57079632679490f
#define F_PIO4    0.78539816339745f

__device__ __forceinline__ float rcp_raw(float x) {
    float r; asm("rcp.approx.f32 %0, %1;" : "=f"(r) : "f"(x)); return r;
}
__device__ __forceinline__ float sqrt_raw(float x) {
    float r; asm("sqrt.approx.f32 %0, %1;" : "=f"(r) : "f"(x)); return r;
}

__device__ __forceinline__ float atan2_pos_full(float y, float x) {
    float ax = fabsf(x);
    float mn = fminf(y, ax);
    float mx = fmaxf(y, ax);
    float t  = mn * rcp_raw(mx);
    bool big = t > 0.41421356f;
    float tb = (t - 1.0f) * rcp_raw(t + 1.0f);
    float t2 = big ? tb : t;
    float z  = t2 * t2;
    float p  = (((8.05374449538e-2f * z - 1.38776856032e-1f) * z
                 + 1.99777106478e-1f) * z - 3.33329491539e-1f) * z * t2 + t2;
    p = big ? p + F_PIO4 : p;
    p = (y > ax) ? F_PIO2 - p : p;
    p = (x < 0.0f) ? F_PI - p : p;
    return p;
}

__device__ __forceinline__ void sincos_delta(float d, float& sd, float& cd) {
    float d2 = d * d;
    sd = d * fmaf(d2, fmaf(d2, fmaf(d2, -1.9841270e-4f, 8.3333333e-3f), -1.6666667e-1f), 1.0f);
    cd = fmaf(d2, fmaf(d2, fmaf(d2, -1.3888889e-3f, 4.1666667e-2f), -0.5f), 1.0f);
}

__device__ __forceinline__ void roundtrip_full(float ax, float ay, float az, float aw,
                                               float& qx, float& qy, float& qz, float& qw,
                                               float& rx, float& ry, float& rz)
{
    float nv2 = ax * ax + ay * ay + az * az;
    float n2  = nv2 + aw * aw;
    float inv = fmaf(-0.5f, n2, 1.5f);
    float nvr = sqrt_raw(nv2);
    float rnvr = rcp_raw(fmaxf(nvr, 1e-30f));
    float alpha = atan2_pos_full(nvr, aw);
    float nv = nvr * inv;
    float w  = aw * inv;
    float rn = rcp_raw(nv + 1e-6f);
    float delta = -1e-6f * alpha * rn;
    float sd, cd;
    sincos_delta(delta, sd, cd);
    float s  = fmaf(nv, cd,  w * sd);
    float c  = fmaf(w,  cd, -nv * sd);
    float ks = s * rnvr;
    bool tiny = nv < 1e-6f;
    qx = tiny ? ax * inv : ax * ks;
    qy = tiny ? ay * inv : ay * ks;
    qz = tiny ? az * inv : az * ks;
    qw = tiny ? 1.0f     : c;

    float klog = tiny ? 2.0f : 2.0f * alpha * rn;
    float ki = klog * inv;
    rx = ki * ax;
    ry = ki * ay;
    rz = ki * az;
}

__device__ __forceinline__ void quat_from_so3(float rx, float ry, float rz,
                                              float& qx, float& qy, float& qz, float& qw)
{
    float t2    = rx * rx + ry * ry + rz * rz;
    float theta = sqrtf(t2);
    float s, c;
    sincosf(0.5f * theta, &s, &c);
    float k = s / (theta + 1e-8f);
    bool small = theta < 1e-6f;
    k  = small ? 0.5f : k;
    qw = small ? 1.0f : c;
    qx = k * rx;
    qy = k * ry;
    qz = k * rz;
}

struct DerivR { float ex, ey, ez, ew, wdx, wdy; };

__device__ __forceinline__ void dyn_rot(float qx, float qy, float qz, float qw,
                                        float wx, float wy, float wz,
                                        float txJ, float tyJ,
                                        DerivR& d)
{
    d.wdx = fmaf(wy * wz, K_C1, txJ);
    d.wdy = fmaf(wz * wx, K_C2, tyJ);

    d.ex = fmaf(qw, wx, fmaf(qy, wz, -(qz * wy)));
    d.ey = fmaf(qw, wy, fmaf(qz, wx, -(qx * wz)));
    d.ez = fmaf(qw, wz, fmaf(qx, wy, -(qy * wx)));
    d.ew = -fmaf(qx, wx, fmaf(qy, wy, qz * wz));
}

// One full RK4 step for one trajectory (R13-validated body). All state by reference.
__device__ __forceinline__ void step_one(float4 um,
                                         float& px, float& py, float& pz,
                                         float& vx, float& vy, float& vz,
                                         float& qx, float& qy, float& qz, float& qw,
                                         float& wx, float& wy, float& wz,
                                         float& rox, float& roy, float& roz)
{
    float m0 = um.x * um.x, m1 = um.y * um.y, m2 = um.z * um.z, m3 = um.w * um.w;
    float T   = K_KT * ((m0 + m1) + (m2 + m3));
    float txJ = (K_KTARM * K_INV_JX) * ((m2 + m3) - (m0 + m1));
    float tyJ = (K_KTARM * K_INV_JX) * ((m1 + m2) - (m0 + m3));
    float tzJ = (K_KC * K_INV_JZ) * ((m0 + m2) - (m1 + m3));

    float t_x = 2.0f * (qy * T);
    float t_y = -2.0f * (qx * T);
    float ax_ = (qw * t_x - qz * t_y) * K_INV_M;
    float ay_ = (qw * t_y + qz * t_x) * K_INV_M;
    float az_ = (T + (qx * t_y - qy * t_x) - K_MG) * K_INV_M;

    float w2z = fmaf(K_HDT, tzJ, wz);
    float w4z = fmaf(K_DT,  tzJ, wz);

    DerivR d1;
    dyn_rot(qx, qy, qz, qw, wx, wy, wz, txJ, tyJ, d1);

    DerivR d2;
    dyn_rot(fmaf(K_A2, d1.ex, qx), fmaf(K_A2, d1.ey, qy),
            fmaf(K_A2, d1.ez, qz), fmaf(K_A2, d1.ew, qw),
            fmaf(K_HDT, d1.wdx, wx), fmaf(K_HDT, d1.wdy, wy), w2z,
            txJ, tyJ, d2);

    DerivR d3;
    dyn_rot(fmaf(K_A2, d2.ex, qx), fmaf(K_A2, d2.ey, qy),
            fmaf(K_A2, d2.ez, qz), fmaf(K_A2, d2.ew, qw),
            fmaf(K_HDT, d2.wdx, wx), fmaf(K_HDT, d2.wdy, wy), w2z,
            txJ, tyJ, d3);

    DerivR d4;
    dyn_rot(fmaf(K_HDT, d3.ex, qx), fmaf(K_HDT, d3.ey, qy),
            fmaf(K_HDT, d3.ez, qz), fmaf(K_HDT, d3.ew, qw),
            fmaf(K_DT, d3.wdx, wx), fmaf(K_DT, d3.wdy, wy), w4z,
            txJ, tyJ, d4);

    float esx = fmaf(2.0f, d3.ex, fmaf(2.0f, d2.ex, d1.ex)) + d4.ex;
    float esy = fmaf(2.0f, d3.ey, fmaf(2.0f, d2.ey, d1.ey)) + d4.ey;
    float esz = fmaf(2.0f, d3.ez, fmaf(2.0f, d2.ez, d1.ez)) + d4.ez;
    float esw = fmaf(2.0f, d3.ew, fmaf(2.0f, d2.ew, d1.ew)) + d4.ew;
    roundtrip_full(fmaf(K_DT12, esx, qx), fmaf(K_DT12, esy, qy),
                   fmaf(K_DT12, esz, qz), fmaf(K_DT12, esw, qw),
                   qx, qy, qz, qw, rox, roy, roz);

    px = px + K_DT * vx + K_DT22 * ax_;
    py = py + K_DT * vy + K_DT22 * ay_;
    pz = pz + K_DT * vz + K_DT22 * az_;

    vx = vx + K_DT * ax_;
    vy = vy + K_DT * ay_;
    vz = vz + K_DT * az_;

    wx = wx + K_DT6 * (fmaf(2.0f, d3.wdx, fmaf(2.0f, d2.wdx, d1.wdx)) + d4.wdx);
    wy = wy + K_DT6 * (fmaf(2.0f, d3.wdy, fmaf(2.0f, d2.wdy, d1.wdy)) + d4.wdy);
    wz = fmaf(K_DT, tzJ, wz);
}

// 2 trajectories per thread: two independent dependency chains interleaved by the
// scheduler fill the ~66% idle issue slots of the single-chain version.
__global__ void __launch_bounds__(32, 1)
quad_rollout_kernel(const float* __restrict__ x0,
                    const float* __restrict__ u_seq,
                    float* __restrict__ out)
{
    int tid = blockIdx.x * 32 + threadIdx.x;
    int b0 = tid * 2;
    int b1 = b0 + 1;
    if (b1 >= BATCH) return;

    const float4* x04 = reinterpret_cast<const float4*>(x0);

    // chain 0 state
    float4 a0 = x04[b0 * 3 + 0], a1 = x04[b0 * 3 + 1], a2 = x04[b0 * 3 + 2];
    float px0 = a0.x, py0 = a0.y, pz0 = a0.z;
    float vx0 = a0.w, vy0 = a1.x, vz0 = a1.y;
    float wx0 = a2.y, wy0 = a2.z, wz0 = a2.w;
    float qx0, qy0, qz0, qw0;
    quat_from_so3(a1.z, a1.w, a2.x, qx0, qy0, qz0, qw0);

    // chain 1 state
    float4 c0 = x04[b1 * 3 + 0], c1 = x04[b1 * 3 + 1], c2 = x04[b1 * 3 + 2];
    float px1 = c0.x, py1 = c0.y, pz1 = c0.z;
    float vx1 = c0.w, vy1 = c1.x, vz1 = c1.y;
    float wx1 = c2.y, wy1 = c2.z, wz1 = c2.w;
    float qx1, qy1, qz1, qw1;
    quat_from_so3(c1.z, c1.w, c2.x, qx1, qy1, qz1, qw1);

    const float4* u40 = reinterpret_cast<const float4*>(u_seq) + (size_t)b0 * NSTEP;
    const float4* u41 = reinterpret_cast<const float4*>(u_seq) + (size_t)b1 * NSTEP;
    float4* o40 = reinterpret_cast<float4*>(out) + (size_t)b0 * NSTEP * 3;
    float4* o41 = reinterpret_cast<float4*>(out) + (size_t)b1 * NSTEP * 3;

    float4 um0 = u40[0];
    float4 um1 = u41[0];

#pragma unroll 1
    for (int t = 0; t < NSTEP; ++t) {
        int tn = (t + 1 < NSTEP) ? (t + 1) : t;
        float4 un0 = u40[tn];
        float4 un1 = u41[tn];

        float rox0, roy0, roz0, rox1, roy1, roz1;
        step_one(um0, px0, py0, pz0, vx0, vy0, vz0,
                 qx0, qy0, qz0, qw0, wx0, wy0, wz0, rox0, roy0, roz0);
        step_one(um1, px1, py1, pz1, vx1, vy1, vz1,
                 qx1, qy1, qz1, qw1, wx1, wy1, wz1, rox1, roy1, roz1);

        o40[t * 3 + 0] = make_float4(px0, py0, pz0, vx0);
        o40[t * 3 + 1] = make_float4(vy0, vz0, rox0, roy0);
        o40[t * 3 + 2] = make_float4(roz0, wx0, wy0, wz0);
        o41[t * 3 + 0] = make_float4(px1, py1, pz1, vx1);
        o41[t * 3 + 1] = make_float4(vy1, vz1, rox1, roy1);
        o41[t * 3 + 2] = make_float4(roz1, wx1, wy1, wz1);

        um0 = un0;
        um1 = un1;
    }
}

extern "C" void kernel_launch(void* const* d_in, const int* in_sizes, int n_in,
                              void* d_out, int out_size)
{
    const float* x0 = (const float*)d_in[0];
    const float* us = (const float*)d_in[1];
    if (n_in >= 2 && in_sizes[0] != BATCH * 12) {
        const float* tmp = x0; x0 = us; us = tmp;
    }
    float* out = (float*)d_out;

    dim3 block(32);
    dim3 grid(BATCH / 64);   // 4096 threads, 2 trajectories each
    quad_rollout_kernel<<<grid, block>>>(x0, us, out);
}